// round 10
// baseline (speedup 1.0000x reference)
#include <cuda_runtime.h>
#include <cuda_fp16.h>
#include <math.h>
#include <cstdint>

// ---------------------------------------------------------------------------
// Problem constants — 64-pixel CTAs, 2 CTAs/SM
// ---------------------------------------------------------------------------
#define C_      32
#define B_      8
#define INCH    201          // K*C*2 + K*K
#define KH      208          // K padded to 13 x 16 (halves)
#define KST     13           // k16 steps
#define NCH     36           // N per chunk (exactly 1 channel x 36)
#define NPAD    40           // padded to 5 n-tiles of 8
#define NCHUNKS 32           // 1152 / 36
#define FSTR_H  216          // feat/B row stride in halves (27 x 16B)
#define FSTR_B  432
#define THREADS 256

// SMEM layout (bytes) — total 110848, x2 CTAs = 221696 <= SM capacity
#define XS_FL    (32*17*17)                 // 9248 floats
#define XS_OFF   0
#define FEAT_OFF 36992                      // 64 * 432 = 27648
#define B0_OFF   65536                      // 1KB aligned
#define BBYTES   (NPAD*FSTR_B)              // 17280
#define B1_OFF   (B0_OFF + BBYTES)          // 82816
#define YB0_OFF  100096
#define YSTR_H2  21                         // ybuf pixel stride in half2 (20+1)
#define YB_BYTES (64*YSTR_H2*4)             // 5376
#define YB1_OFF  (YB0_OFF + YB_BYTES)       // 105472
#define SMEM_BYTES (YB1_OFF + YB_BYTES)     // 110848

// ---------------------------------------------------------------------------
// Static scratch (no allocations)
// ---------------------------------------------------------------------------
__device__ __half g_wh[1152 * KH];   // BN-folded fp16 weights, K-padded
__device__ float  g_bias[1152];

// ---------------------------------------------------------------------------
// PTX helpers (sm_103 BASE features only)
// ---------------------------------------------------------------------------
__device__ __forceinline__ uint32_t su32(const void* p) {
    uint32_t a;
    asm("{ .reg .u64 t; cvta.to.shared.u64 t, %1; cvt.u32.u64 %0, t; }" : "=r"(a) : "l"(p));
    return a;
}
__device__ __forceinline__ void ldsm4(uint32_t* r, uint32_t a) {
    asm volatile("ldmatrix.sync.aligned.m8n8.x4.shared.b16 {%0,%1,%2,%3}, [%4];"
                 : "=r"(r[0]), "=r"(r[1]), "=r"(r[2]), "=r"(r[3]) : "r"(a));
}
__device__ __forceinline__ void ldsm2(uint32_t* r, uint32_t a) {
    asm volatile("ldmatrix.sync.aligned.m8n8.x2.shared.b16 {%0,%1}, [%2];"
                 : "=r"(r[0]), "=r"(r[1]) : "r"(a));
}
__device__ __forceinline__ void mma16816(float* c, const uint32_t* a, const uint32_t* b) {
    asm volatile("mma.sync.aligned.m16n8k16.row.col.f32.f16.f16.f32 "
                 "{%0,%1,%2,%3}, {%4,%5,%6,%7}, {%8,%9}, {%0,%1,%2,%3};"
                 : "+f"(c[0]), "+f"(c[1]), "+f"(c[2]), "+f"(c[3])
                 : "r"(a[0]), "r"(a[1]), "r"(a[2]), "r"(a[3]), "r"(b[0]), "r"(b[1]));
}
__device__ __forceinline__ void cpasync16(uint32_t dst, const void* src) {
    asm volatile("cp.async.cg.shared.global [%0], [%1], 16;" :: "r"(dst), "l"(src));
}
__device__ __forceinline__ void cpcommit() { asm volatile("cp.async.commit_group;"); }
__device__ __forceinline__ void cpwait1()  { asm volatile("cp.async.wait_group 1;" ::: "memory"); }

// ---------------------------------------------------------------------------
// Repack: fold BN into conv_w, convert fp16, pad K 201->208
// ---------------------------------------------------------------------------
__global__ void repack_kernel(const float* __restrict__ w,
                              const float* __restrict__ gamma,
                              const float* __restrict__ beta,
                              const float* __restrict__ mean,
                              const float* __restrict__ var) {
    int m = blockIdx.x;
    float sc = gamma[m] * rsqrtf(var[m] + 1e-5f);
    if (threadIdx.x == 0) g_bias[m] = beta[m] - mean[m] * sc;
    for (int k = threadIdx.x; k < KH; k += blockDim.x) {
        float v = (k < INCH) ? w[m * INCH + k] * sc : 0.f;
        g_wh[m * KH + k] = __float2half_rn(v);
    }
}

// Stage one 36-row N-chunk (rows 36..39 are pre-zeroed pad)
__device__ __forceinline__ void stage_b(uint32_t bufs, int n0, int tid) {
    for (int e = tid; e < NCH * 26; e += THREADS) {
        int r = e / 26, q = e - r * 26;
        cpasync16(bufs + r * FSTR_B + q * 16,
                  g_wh + (size_t)(n0 + r) * KH + q * 8);
    }
}

// ---------------------------------------------------------------------------
// One N-chunk GEMM with register-resident A: warp = M16 x NT n-tiles, K=208
// ---------------------------------------------------------------------------
template <int NT>
__device__ __forceinline__ void gemm_chunk(const uint32_t afr[KST][4],
                                           uint32_t bbase, int lane,
                                           float acc[][4]) {
    #pragma unroll
    for (int s = 0; s < KST; ++s) {
        uint32_t bf[NT][2];
        #pragma unroll
        for (int pq = 0; pq < NT / 2; ++pq) {
            uint32_t ad = bbase
                        + (uint32_t)((pq * 2 + (lane >> 4)) * 8 + (lane & 7)) * FSTR_B
                        + s * 32 + ((lane >> 3) & 1) * 16;
            uint32_t t4[4];
            ldsm4(t4, ad);
            bf[2 * pq][0] = t4[0]; bf[2 * pq][1] = t4[1];
            bf[2 * pq + 1][0] = t4[2]; bf[2 * pq + 1][1] = t4[3];
        }
        if (NT & 1) {
            uint32_t ad = bbase + (uint32_t)((NT - 1) * 8 + (lane & 7)) * FSTR_B
                        + s * 32 + ((lane >> 3) & 1) * 16;
            ldsm2(bf[NT - 1], ad);
        }
        #pragma unroll
        for (int nt = 0; nt < NT; ++nt)
            mma16816(acc[nt], afr[s], bf[nt]);
    }
}

// ---------------------------------------------------------------------------
// Fused epilogue for chunk t (= channel t): thread = (pixel, u, v)
// ---------------------------------------------------------------------------
__device__ __forceinline__ void epilogue(int t, const __half2* ybh2,
                                         const float* xs, float* out, int tid,
                                         int b, int oy0, int ox0) {
    const int p = tid >> 2, uv = tid & 3, u = uv >> 1, v = uv & 1;
    const int oyl = p >> 3, oxl = p & 7;
    const float* xc = xs + t * 289 + (2 * oyl) * 17 + 2 * oxl;
    float ph[9];
    #pragma unroll
    for (int ki = 0; ki < 3; ++ki)
        #pragma unroll
        for (int kj = 0; kj < 3; ++kj) ph[ki * 3 + kj] = xc[ki * 17 + kj];
    const __half2* yb = ybh2 + p * YSTR_H2 + u;
    const float* bs = g_bias + t * 36 + uv;
    float o = 0.f;
    #pragma unroll
    for (int kk = 0; kk < 9; ++kk) {
        float2 yp = __half22float2(yb[kk * 2]);
        float y = (v == 0) ? yp.x : yp.y;
        o += ph[kk] * fmaxf(y + __ldg(bs + kk * 4), 0.f);
    }
    out[((size_t)(b * C_ + t) * 128 + 2 * (oy0 + oyl) + u) * 128
        + 2 * (ox0 + oxl) + v] = o * (1.f / 9.f);
}

// ---------------------------------------------------------------------------
// Main fused kernel: CTA = 64 pixels (8x8), 2 CTAs/SM
// ---------------------------------------------------------------------------
__global__ __launch_bounds__(THREADS, 2)
void revo_hmma(const float* __restrict__ x, float* __restrict__ out) {
    extern __shared__ char smem[];
    float*  xs   = (float*)(smem + XS_OFF);
    __half* feat = (__half*)(smem + FEAT_OFF);
    float*  scr  = (float*)(smem + YB0_OFF);   // cm partials, pre-loop only
    const uint32_t sb = su32(smem);

    const int tid = threadIdx.x, lane = tid & 31, wid = tid >> 5;
    const int b = blockIdx.z, oy0 = blockIdx.y * 8, ox0 = blockIdx.x * 8;

    // stage weight chunk 0 early
    stage_b(sb + B0_OFF, 0, tid);
    cpcommit();

    // zero pad rows 36..39 of both B buffers (ldsm touches them; mma sees 0)
    for (int e = tid; e < 2 * 4 * 27; e += THREADS) {
        int buf = e / 108, r = (e / 27) & 3, q = e % 27;
        *(uint4*)(smem + (buf ? B1_OFF : B0_OFF) + (36 + r) * FSTR_B + q * 16) =
            make_uint4(0, 0, 0, 0);
    }

    // ---- x tile [32][17][17], zero-padded halo ----
    const float* xb = x + (size_t)b * C_ * 16384;
    for (int e = tid; e < XS_FL; e += THREADS) {
        int c = e / 289, rem = e - c * 289;
        int yy = rem / 17, xx = rem - yy * 17;
        int iy = 2 * oy0 - 1 + yy, ix = 2 * ox0 - 1 + xx;
        float v = 0.f;
        if ((unsigned)iy < 128u && (unsigned)ix < 128u) v = xb[c * 16384 + iy * 128 + ix];
        xs[e] = v;
    }
    __syncthreads();

    // ---- feat build, parallel over (pixel, 8-channel group) ----
    {
        const int p = tid & 63, cg = tid >> 6;   // cg = 0..3
        const int oyl = p >> 3, oxl = p & 7;
        const int pb = (2 * oyl) * 17 + 2 * oxl;
        __half* fr = feat + p * FSTR_H;
        float cm[9];
        #pragma unroll
        for (int kk = 0; kk < 9; ++kk) cm[kk] = -3.402823466e38f;
        #pragma unroll
        for (int cc = 0; cc < 8; ++cc) {
            const int c = cg * 8 + cc;
            const float* xc = xs + c * 289 + pb;
            float ph[9];
            #pragma unroll
            for (int ki = 0; ki < 3; ++ki)
                #pragma unroll
                for (int kj = 0; kj < 3; ++kj) ph[ki * 3 + kj] = xc[ki * 17 + kj];
            #pragma unroll
            for (int kk = 0; kk < 9; ++kk) cm[kk] = fmaxf(cm[kk], ph[kk]);
            #pragma unroll
            for (int j = 0; j < 3; ++j)
                fr[9 + c * 3 + j] =
                    __float2half_rn(fmaxf(fmaxf(ph[j], ph[3 + j]), ph[6 + j]));
            #pragma unroll
            for (int i = 0; i < 3; ++i)
                fr[105 + c * 3 + i] =
                    __float2half_rn(fmaxf(fmaxf(ph[3 * i], ph[3 * i + 1]), ph[3 * i + 2]));
        }
        #pragma unroll
        for (int kk = 0; kk < 9; ++kk) scr[p * 36 + cg * 9 + kk] = cm[kk];
    }
    __syncthreads();
    for (int e = tid; e < 64 * 9; e += THREADS) {
        int p = e / 9, kk = e - p * 9;
        feat[p * FSTR_H + kk] = __float2half_rn(
            fmaxf(fmaxf(scr[p * 36 + kk],      scr[p * 36 + 9 + kk]),
                  fmaxf(scr[p * 36 + 18 + kk], scr[p * 36 + 27 + kk])));
    }
    if (tid < 64) {
        #pragma unroll
        for (int k = INCH; k < KH; ++k)
            feat[tid * FSTR_H + k] = __ushort_as_half(0);
    }
    __syncthreads();

    // warp tiling: 4 M-groups (16 rows) x 2 N-groups (3 / 2 n-tiles of 5)
    const int m0 = (wid >> 1) * 16;
    const int ngrp = wid & 1;
    const int tb = ngrp ? 3 : 0;
    const int g = lane >> 2, tg = lane & 3;

    // preload A fragments (feat invariant across chunks): 52 regs
    uint32_t afr[KST][4];
    #pragma unroll
    for (int s = 0; s < KST; ++s)
        ldsm4(afr[s], sb + FEAT_OFF + (uint32_t)(m0 + (lane & 15)) * FSTR_B
                      + s * 32 + (lane >> 4) * 16);

    // ---- pipelined loop: stage(t+1) | GEMM(t) | epilogue(t-1) ----
    for (int t = 0; t < NCHUNKS; ++t) {
        if (t + 1 < NCHUNKS)
            stage_b(sb + (((t + 1) & 1) ? B1_OFF : B0_OFF), (t + 1) * NCH, tid);
        cpcommit();
        cpwait1();

        const uint32_t bb = sb + ((t & 1) ? B1_OFF : B0_OFF);
        float acc[3][4];
        #pragma unroll
        for (int i = 0; i < 3; ++i)
            #pragma unroll
            for (int k = 0; k < 4; ++k) acc[i][k] = 0.f;

        if (ngrp == 0) gemm_chunk<3>(afr, bb, lane, acc);
        else           gemm_chunk<2>(afr, bb + 3 * 8 * FSTR_B, lane, acc);

        // C frags -> ybuf[t&1] as half2
        __half2* ybw = (__half2*)(smem + ((t & 1) ? YB1_OFF : YB0_OFF));
        const int NTloc = ngrp ? 2 : 3;
        #pragma unroll
        for (int nt = 0; nt < 3; ++nt) {
            if (nt < NTloc) {
                int h2i = (tb + nt) * 4 + tg;
                ybw[(m0 + g) * YSTR_H2 + h2i] =
                    __floats2half2_rn(acc[nt][0], acc[nt][1]);
                ybw[(m0 + g + 8) * YSTR_H2 + h2i] =
                    __floats2half2_rn(acc[nt][2], acc[nt][3]);
            }
        }

        if (t > 0)
            epilogue(t - 1,
                     (const __half2*)(smem + (((t - 1) & 1) ? YB1_OFF : YB0_OFF)),
                     xs, out, tid, b, oy0, ox0);
        __syncthreads();
    }
    epilogue(NCHUNKS - 1,
             (const __half2*)(smem + (((NCHUNKS - 1) & 1) ? YB1_OFF : YB0_OFF)),
             xs, out, tid, b, oy0, ox0);
}

// ---------------------------------------------------------------------------
extern "C" void kernel_launch(void* const* d_in, const int* in_sizes, int n_in,
                              void* d_out, int out_size) {
    const float* x   = (const float*)d_in[0];
    const float* cw  = (const float*)d_in[1];
    const float* gam = (const float*)d_in[2];
    const float* bet = (const float*)d_in[3];
    const float* mn  = (const float*)d_in[4];
    const float* vr  = (const float*)d_in[5];
    float* out       = (float*)d_out;

    cudaFuncSetAttribute(revo_hmma, cudaFuncAttributeMaxDynamicSharedMemorySize,
                         SMEM_BYTES);

    repack_kernel<<<1152, 128>>>(cw, gam, bet, mn, vr);
    dim3 grid(8, 8, B_);   // 8x8 pixel tiles x batch = 512 CTAs
    revo_hmma<<<grid, THREADS, SMEM_BYTES>>>(x, out);
}

// round 11
// speedup vs baseline: 1.1846x; 1.1846x over previous
#include <cuda_runtime.h>
#include <cuda_fp16.h>
#include <math.h>
#include <cstdint>

// ---------------------------------------------------------------------------
// Problem constants — 128-pixel CTAs, 2 CTAs/SM, x read from global
// ---------------------------------------------------------------------------
#define C_      32
#define B_      8
#define INCH    201          // K*C*2 + K*K
#define KH      208          // K padded to 13 x 16 (halves)
#define KST     13           // k16 steps
#define NCH     36           // N per chunk (exactly 1 channel x 36)
#define NPAD    40           // padded to 5 n-tiles of 8
#define NCHUNKS 32           // 1152 / 36
#define FSTR_H  216          // feat row stride in halves (27 x 16B, conflict-free)
#define FSTR_B  432
#define THREADS 256

// SMEM layout (bytes) — 109312 total, x2 CTAs = 218624 <= 228KB
#define FEAT_OFF 0                          // 128 * 432 = 55296
#define B0_OFF   55296
#define BBYTES   (NPAD*FSTR_B)              // 17280
#define B1_OFF   (B0_OFF + BBYTES)          // 72576
#define YB0_OFF  89856
#define YSTR_H2  19                         // ybuf pixel stride in half2
#define YB_BYTES (128*YSTR_H2*4)            // 9728
#define YB1_OFF  (YB0_OFF + YB_BYTES)       // 99584
#define SMEM_BYTES (YB1_OFF + YB_BYTES)     // 109312

// ---------------------------------------------------------------------------
// Static scratch (no allocations)
// ---------------------------------------------------------------------------
__device__ __half g_wh[1152 * KH];   // BN-folded fp16 weights, K-padded
__device__ float  g_bias[1152];

// ---------------------------------------------------------------------------
// PTX helpers (sm_103 BASE features only)
// ---------------------------------------------------------------------------
__device__ __forceinline__ uint32_t su32(const void* p) {
    uint32_t a;
    asm("{ .reg .u64 t; cvta.to.shared.u64 t, %1; cvt.u32.u64 %0, t; }" : "=r"(a) : "l"(p));
    return a;
}
__device__ __forceinline__ void ldsm4(uint32_t* r, uint32_t a) {
    asm volatile("ldmatrix.sync.aligned.m8n8.x4.shared.b16 {%0,%1,%2,%3}, [%4];"
                 : "=r"(r[0]), "=r"(r[1]), "=r"(r[2]), "=r"(r[3]) : "r"(a));
}
__device__ __forceinline__ void ldsm2(uint32_t* r, uint32_t a) {
    asm volatile("ldmatrix.sync.aligned.m8n8.x2.shared.b16 {%0,%1}, [%2];"
                 : "=r"(r[0]), "=r"(r[1]) : "r"(a));
}
__device__ __forceinline__ void mma16816(float* c, const uint32_t* a, const uint32_t* b) {
    asm volatile("mma.sync.aligned.m16n8k16.row.col.f32.f16.f16.f32 "
                 "{%0,%1,%2,%3}, {%4,%5,%6,%7}, {%8,%9}, {%0,%1,%2,%3};"
                 : "+f"(c[0]), "+f"(c[1]), "+f"(c[2]), "+f"(c[3])
                 : "r"(a[0]), "r"(a[1]), "r"(a[2]), "r"(a[3]), "r"(b[0]), "r"(b[1]));
}
__device__ __forceinline__ void cpasync16(uint32_t dst, const void* src) {
    asm volatile("cp.async.cg.shared.global [%0], [%1], 16;" :: "r"(dst), "l"(src));
}
__device__ __forceinline__ void cpcommit() { asm volatile("cp.async.commit_group;"); }
__device__ __forceinline__ void cpwait1()  { asm volatile("cp.async.wait_group 1;" ::: "memory"); }

// ---------------------------------------------------------------------------
// Repack: fold BN into conv_w, convert fp16, pad K 201->208
// ---------------------------------------------------------------------------
__global__ void repack_kernel(const float* __restrict__ w,
                              const float* __restrict__ gamma,
                              const float* __restrict__ beta,
                              const float* __restrict__ mean,
                              const float* __restrict__ var) {
    int m = blockIdx.x;
    float sc = gamma[m] * rsqrtf(var[m] + 1e-5f);
    if (threadIdx.x == 0) g_bias[m] = beta[m] - mean[m] * sc;
    for (int k = threadIdx.x; k < KH; k += blockDim.x) {
        float v = (k < INCH) ? w[m * INCH + k] * sc : 0.f;
        g_wh[m * KH + k] = __float2half_rn(v);
    }
}

// Stage one 36-row N-chunk (rows 36..39 pre-zeroed pad, never overwritten)
__device__ __forceinline__ void stage_b(uint32_t bufs, int n0, int tid) {
    for (int e = tid; e < NCH * 26; e += THREADS) {
        int r = e / 26, q = e - r * 26;
        cpasync16(bufs + r * FSTR_B + q * 16,
                  g_wh + (size_t)(n0 + r) * KH + q * 8);
    }
}

// ---------------------------------------------------------------------------
// One N-chunk GEMM, register-resident A: warp = M16 x 5 n-tiles, K=208
// ---------------------------------------------------------------------------
__device__ __forceinline__ void gemm_chunk(const uint32_t afr[KST][4],
                                           uint32_t bbase, int lane,
                                           float acc[5][4]) {
    #pragma unroll
    for (int s = 0; s < KST; ++s) {
        uint32_t bf[5][2];
        #pragma unroll
        for (int pq = 0; pq < 2; ++pq) {
            uint32_t ad = bbase
                        + (uint32_t)((pq * 2 + (lane >> 4)) * 8 + (lane & 7)) * FSTR_B
                        + s * 32 + ((lane >> 3) & 1) * 16;
            uint32_t t4[4];
            ldsm4(t4, ad);
            bf[2 * pq][0] = t4[0]; bf[2 * pq][1] = t4[1];
            bf[2 * pq + 1][0] = t4[2]; bf[2 * pq + 1][1] = t4[3];
        }
        {
            uint32_t ad = bbase + (uint32_t)(4 * 8 + (lane & 7)) * FSTR_B
                        + s * 32 + ((lane >> 3) & 1) * 16;
            ldsm2(bf[4], ad);
        }
        #pragma unroll
        for (int nt = 0; nt < 5; ++nt)
            mma16816(acc[nt], afr[s], bf[nt]);
    }
}

// ---------------------------------------------------------------------------
// Fused epilogue for chunk t (= channel t): thread = (pixel, uv-half)
// ---------------------------------------------------------------------------
__device__ __forceinline__ void epilogue(int t, const __half2* ybh2,
                                         const float* __restrict__ x,
                                         float* __restrict__ out, int tid,
                                         int b, int oy0, int ox0) {
    const int p = tid >> 1, h = tid & 1;
    const int oyl = p >> 3, oxl = p & 7;
    const int oy = oy0 + oyl, ox = ox0 + oxl;
    const float* xc = x + ((size_t)(b * C_ + t) * 128) * 128;
    float ph[9];
    #pragma unroll
    for (int ki = 0; ki < 3; ++ki) {
        int iy = 2 * oy - 1 + ki;
        #pragma unroll
        for (int kj = 0; kj < 3; ++kj) {
            int ix = 2 * ox - 1 + kj;
            float v = 0.f;
            if ((unsigned)iy < 128u && (unsigned)ix < 128u)
                v = __ldg(xc + iy * 128 + ix);
            ph[ki * 3 + kj] = v;
        }
    }
    const __half2* yb = ybh2 + p * YSTR_H2 + h;
    const float* bs = g_bias + t * 36 + 2 * h;
    float o0 = 0.f, o1 = 0.f;
    #pragma unroll
    for (int kk = 0; kk < 9; ++kk) {
        const float pv = ph[kk];
        float2 yp = __half22float2(yb[kk * 2]);
        float2 bb = *(const float2*)(bs + kk * 4);
        o0 += pv * fmaxf(yp.x + bb.x, 0.f);
        o1 += pv * fmaxf(yp.y + bb.y, 0.f);
    }
    const float inv9 = 1.f / 9.f;
    const size_t ob = ((size_t)(b * C_ + t) * 128 + 2 * oy + h) * 128 + 2 * ox;
    *(float2*)(out + ob) = make_float2(o0 * inv9, o1 * inv9);
}

// ---------------------------------------------------------------------------
// Main fused kernel: CTA = 128 pixels (16 oy x 8 ox), 2 CTAs/SM
// ---------------------------------------------------------------------------
__global__ __launch_bounds__(THREADS, 2)
void revo_hmma(const float* __restrict__ x, float* __restrict__ out) {
    extern __shared__ char smem[];
    __half* feat = (__half*)(smem + FEAT_OFF);
    float*  scr  = (float*)(smem + YB0_OFF);   // cm partials, prologue only
    const uint32_t sb = su32(smem);

    const int tid = threadIdx.x, lane = tid & 31, wid = tid >> 5;
    const int b = blockIdx.z, oy0 = blockIdx.y * 16, ox0 = blockIdx.x * 8;

    // stage weight chunk 0 early; zero the 4 pad rows of both B buffers
    stage_b(sb + B0_OFF, 0, tid);
    cpcommit();
    for (int e = tid; e < 2 * 4 * 27; e += THREADS) {
        int buf = e / 108, r = (e / 27) & 3, q = e % 27;
        *(uint4*)(smem + (buf ? B1_OFF : B0_OFF) + (36 + r) * FSTR_B + q * 16) =
            make_uint4(0, 0, 0, 0);
    }

    // ---- feat build from GLOBAL x, parallel over (pixel, 16-channel group) --
    {
        const int p = tid & 127, cg = tid >> 7;   // cg = 0/1
        const int oyl = p >> 3, oxl = p & 7;
        const int oy = oy0 + oyl, ox = ox0 + oxl;
        __half* fr = feat + p * FSTR_H;
        int iy[3], ix[3];
        bool oky[3], okx[3];
        #pragma unroll
        for (int k3 = 0; k3 < 3; ++k3) {
            iy[k3] = 2 * oy - 1 + k3; oky[k3] = (unsigned)iy[k3] < 128u;
            ix[k3] = 2 * ox - 1 + k3; okx[k3] = (unsigned)ix[k3] < 128u;
        }
        float cm[9];
        #pragma unroll
        for (int kk = 0; kk < 9; ++kk) cm[kk] = -3.402823466e38f;
        #pragma unroll
        for (int cc = 0; cc < 16; ++cc) {
            const int c = cg * 16 + cc;
            const float* xc = x + ((size_t)(b * C_ + c) * 128) * 128;
            float ph[9];
            #pragma unroll
            for (int ki = 0; ki < 3; ++ki)
                #pragma unroll
                for (int kj = 0; kj < 3; ++kj) {
                    float v = 0.f;
                    if (oky[ki] && okx[kj]) v = __ldg(xc + iy[ki] * 128 + ix[kj]);
                    ph[ki * 3 + kj] = v;
                }
            #pragma unroll
            for (int kk = 0; kk < 9; ++kk) cm[kk] = fmaxf(cm[kk], ph[kk]);
            #pragma unroll
            for (int j = 0; j < 3; ++j)   // max over kernel rows
                fr[9 + c * 3 + j] =
                    __float2half_rn(fmaxf(fmaxf(ph[j], ph[3 + j]), ph[6 + j]));
            #pragma unroll
            for (int i = 0; i < 3; ++i)   // max over kernel cols
                fr[105 + c * 3 + i] =
                    __float2half_rn(fmaxf(fmaxf(ph[3 * i], ph[3 * i + 1]), ph[3 * i + 2]));
        }
        #pragma unroll
        for (int kk = 0; kk < 9; ++kk) scr[p * 18 + cg * 9 + kk] = cm[kk];
    }
    __syncthreads();
    for (int e = tid; e < 128 * 9; e += THREADS) {
        int p = e / 9, kk = e - p * 9;
        feat[p * FSTR_H + kk] =
            __float2half_rn(fmaxf(scr[p * 18 + kk], scr[p * 18 + 9 + kk]));
    }
    if (tid < 128) {
        #pragma unroll
        for (int k = INCH; k < KH; ++k)
            feat[tid * FSTR_H + k] = __ushort_as_half(0);
    }
    __syncthreads();

    // warp tiling: 8 M-groups of 16 rows, each warp covers all 5 n-tiles
    const int m0 = wid * 16;
    const int g = lane >> 2, tg = lane & 3;

    // preload A fragments (feat invariant across all 32 chunks): 52 regs
    uint32_t afr[KST][4];
    #pragma unroll
    for (int s = 0; s < KST; ++s)
        ldsm4(afr[s], sb + FEAT_OFF + (uint32_t)(m0 + (lane & 15)) * FSTR_B
                      + s * 32 + (lane >> 4) * 16);

    // ---- pipelined loop: stage(t+1) | GEMM(t) | epilogue(t-1) ----
    for (int t = 0; t < NCHUNKS; ++t) {
        if (t + 1 < NCHUNKS)
            stage_b(sb + (((t + 1) & 1) ? B1_OFF : B0_OFF), (t + 1) * NCH, tid);
        cpcommit();
        cpwait1();

        const uint32_t bb = sb + ((t & 1) ? B1_OFF : B0_OFF);
        float acc[5][4];
        #pragma unroll
        for (int i = 0; i < 5; ++i)
            #pragma unroll
            for (int k = 0; k < 4; ++k) acc[i][k] = 0.f;

        gemm_chunk(afr, bb, lane, acc);

        // C frags -> ybuf[t&1] as half2 (n = 2*(nt*4+tg), valid n < 36)
        __half2* ybw = (__half2*)(smem + ((t & 1) ? YB1_OFF : YB0_OFF));
        #pragma unroll
        for (int nt = 0; nt < 5; ++nt) {
            int h2i = nt * 4 + tg;
            if (h2i < 18) {
                ybw[(m0 + g) * YSTR_H2 + h2i] =
                    __floats2half2_rn(acc[nt][0], acc[nt][1]);
                ybw[(m0 + g + 8) * YSTR_H2 + h2i] =
                    __floats2half2_rn(acc[nt][2], acc[nt][3]);
            }
        }

        if (t > 0)
            epilogue(t - 1,
                     (const __half2*)(smem + (((t - 1) & 1) ? YB1_OFF : YB0_OFF)),
                     x, out, tid, b, oy0, ox0);
        __syncthreads();
    }
    epilogue(NCHUNKS - 1,
             (const __half2*)(smem + (((NCHUNKS - 1) & 1) ? YB1_OFF : YB0_OFF)),
             x, out, tid, b, oy0, ox0);
}

// ---------------------------------------------------------------------------
extern "C" void kernel_launch(void* const* d_in, const int* in_sizes, int n_in,
                              void* d_out, int out_size) {
    const float* x   = (const float*)d_in[0];
    const float* cw  = (const float*)d_in[1];
    const float* gam = (const float*)d_in[2];
    const float* bet = (const float*)d_in[3];
    const float* mn  = (const float*)d_in[4];
    const float* vr  = (const float*)d_in[5];
    float* out       = (float*)d_out;

    cudaFuncSetAttribute(revo_hmma, cudaFuncAttributeMaxDynamicSharedMemorySize,
                         SMEM_BYTES);

    repack_kernel<<<1152, 128>>>(cw, gam, bet, mn, vr);
    dim3 grid(8, 4, B_);   // 256 CTAs, 2 resident per SM -> single wave
    revo_hmma<<<grid, THREADS, SMEM_BYTES>>>(x, out);
}

// round 13
// speedup vs baseline: 1.2180x; 1.0281x over previous
#include <cuda_runtime.h>
#include <cuda_fp16.h>
#include <math.h>
#include <cstdint>

// ---------------------------------------------------------------------------
// Problem constants — 128-px CTAs, 2 CTAs/SM, warp K-split GEMM
// ---------------------------------------------------------------------------
#define C_      32
#define B_      8
#define INCH    201          // K*C*2 + K*K
#define KH      208          // K padded to 13 x 16 (halves)
#define KST     13           // k16 steps (split 7 / 6 across warp K-groups)
#define NCH     36           // N per chunk (exactly 1 channel x 36)
#define NPAD    40           // padded to 5 n-tiles of 8
#define NCHUNKS 32           // 1152 / 36
#define FSTR_H  216          // feat row stride in halves (27 x 16B)
#define FSTR_B  432
#define THREADS 256

// SMEM layout (bytes) — 89856 total, x2 CTAs = 179712
#define B0_OFF   0
#define BBYTES   (NPAD*FSTR_B)              // 17280
#define B1_OFF   BBYTES                     // 17280 (scr borrows this in prologue)
#define FEAT_OFF (2*BBYTES)                 // 34560
#define FEAT_BYTES (128*FSTR_B)             // 55296
#define SMEM_BYTES (FEAT_OFF + FEAT_BYTES)  // 89856
// ybuf reuses the feat region once A-fragments are register-resident:
// [buf(2)][kgrp(2)][128 px][YSTR_H2 half2]
#define YB_OFF   FEAT_OFF
#define YSTR_H2  20                         // conflict-free stores
#define YKG_H2   (128*YSTR_H2)              // 2560 half2 per kgrp plane
#define YKG_BYTES (YKG_H2*4)                // 10240
#define YBUF_BYTES (2*YKG_BYTES)            // 20480 (two planes); x2 bufs = 40960

// ---------------------------------------------------------------------------
// Static scratch (no allocations)
// ---------------------------------------------------------------------------
__device__ __half g_wh[1152 * KH];   // BN-folded fp16 weights, K-padded
__device__ float  g_bias[1152];

// ---------------------------------------------------------------------------
// PTX helpers (sm_103 BASE features only)
// ---------------------------------------------------------------------------
__device__ __forceinline__ uint32_t su32(const void* p) {
    uint32_t a;
    asm("{ .reg .u64 t; cvta.to.shared.u64 t, %1; cvt.u32.u64 %0, t; }" : "=r"(a) : "l"(p));
    return a;
}
__device__ __forceinline__ void ldsm4(uint32_t* r, uint32_t a) {
    asm volatile("ldmatrix.sync.aligned.m8n8.x4.shared.b16 {%0,%1,%2,%3}, [%4];"
                 : "=r"(r[0]), "=r"(r[1]), "=r"(r[2]), "=r"(r[3]) : "r"(a));
}
__device__ __forceinline__ void ldsm2(uint32_t* r, uint32_t a) {
    asm volatile("ldmatrix.sync.aligned.m8n8.x2.shared.b16 {%0,%1}, [%2];"
                 : "=r"(r[0]), "=r"(r[1]) : "r"(a));
}
__device__ __forceinline__ void mma16816(float* c, const uint32_t* a, const uint32_t* b) {
    asm volatile("mma.sync.aligned.m16n8k16.row.col.f32.f16.f16.f32 "
                 "{%0,%1,%2,%3}, {%4,%5,%6,%7}, {%8,%9}, {%0,%1,%2,%3};"
                 : "+f"(c[0]), "+f"(c[1]), "+f"(c[2]), "+f"(c[3])
                 : "r"(a[0]), "r"(a[1]), "r"(a[2]), "r"(a[3]), "r"(b[0]), "r"(b[1]));
}
__device__ __forceinline__ void cpasync16(uint32_t dst, const void* src) {
    asm volatile("cp.async.cg.shared.global [%0], [%1], 16;" :: "r"(dst), "l"(src));
}
__device__ __forceinline__ void cpcommit() { asm volatile("cp.async.commit_group;"); }
__device__ __forceinline__ void cpwait1()  { asm volatile("cp.async.wait_group 1;" ::: "memory"); }

// ---------------------------------------------------------------------------
// Repack: fold BN into conv_w, convert fp16, pad K 201->208
// ---------------------------------------------------------------------------
__global__ void repack_kernel(const float* __restrict__ w,
                              const float* __restrict__ gamma,
                              const float* __restrict__ beta,
                              const float* __restrict__ mean,
                              const float* __restrict__ var) {
    int m = blockIdx.x;
    float sc = gamma[m] * rsqrtf(var[m] + 1e-5f);
    if (threadIdx.x == 0) g_bias[m] = beta[m] - mean[m] * sc;
    for (int k = threadIdx.x; k < KH; k += blockDim.x) {
        float v = (k < INCH) ? w[m * INCH + k] * sc : 0.f;
        g_wh[m * KH + k] = __float2half_rn(v);
    }
}

// Stage one 36-row N-chunk (rows 36..39 pre-zeroed pad, never overwritten)
__device__ __forceinline__ void stage_b(uint32_t bufs, int n0, int tid) {
    for (int e = tid; e < NCH * 26; e += THREADS) {
        int r = e / 26, q = e - r * 26;
        cpasync16(bufs + r * FSTR_B + q * 16,
                  g_wh + (size_t)(n0 + r) * KH + q * 8);
    }
}

// ---------------------------------------------------------------------------
// K-split chunk GEMM: warp = M32 (2 m-tiles) x 5 n-tiles over its K half.
// A is register-resident (only this warp's ksteps). nks/ks0 warp-uniform.
// ---------------------------------------------------------------------------
__device__ __forceinline__ void gemm_chunk(const uint32_t afr[7][2][4],
                                           int ks0, int nks,
                                           uint32_t bbase, int lane,
                                           float acc[5][2][4]) {
    #pragma unroll
    for (int i = 0; i < 7; ++i) {
        if (i < nks) {
            const int s = ks0 + i;
            uint32_t bf[5][2];
            #pragma unroll
            for (int pq = 0; pq < 2; ++pq) {
                uint32_t ad = bbase
                            + (uint32_t)((pq * 2 + (lane >> 4)) * 8 + (lane & 7)) * FSTR_B
                            + s * 32 + ((lane >> 3) & 1) * 16;
                uint32_t t4[4];
                ldsm4(t4, ad);
                bf[2 * pq][0] = t4[0]; bf[2 * pq][1] = t4[1];
                bf[2 * pq + 1][0] = t4[2]; bf[2 * pq + 1][1] = t4[3];
            }
            {
                uint32_t ad = bbase + (uint32_t)(4 * 8 + (lane & 7)) * FSTR_B
                            + s * 32 + ((lane >> 3) & 1) * 16;
                ldsm2(bf[4], ad);
            }
            #pragma unroll
            for (int nt = 0; nt < 5; ++nt)
                #pragma unroll
                for (int mt = 0; mt < 2; ++mt)
                    mma16816(acc[nt][mt], afr[i][mt], bf[nt]);
        }
    }
}

// ---------------------------------------------------------------------------
// Fused epilogue chunk t (= channel t): thread = (pixel, uv-half).
// y = partial(kgrp0) + partial(kgrp1) + bias, then relu, patch-weighted mean.
// ---------------------------------------------------------------------------
__device__ __forceinline__ void epilogue(int t, const char* ybase,
                                         const float* __restrict__ x,
                                         float* __restrict__ out, int tid,
                                         int b, int oy0, int ox0) {
    const int p = tid >> 1, h = tid & 1;
    const int oyl = p >> 3, oxl = p & 7;
    const int oy = oy0 + oyl, ox = ox0 + oxl;
    const float* xc = x + ((size_t)(b * C_ + t) * 128) * 128;
    float ph[9];
    #pragma unroll
    for (int ki = 0; ki < 3; ++ki) {
        int iy = 2 * oy - 1 + ki;
        #pragma unroll
        for (int kj = 0; kj < 3; ++kj) {
            int ix = 2 * ox - 1 + kj;
            float v = 0.f;
            if ((unsigned)iy < 128u && (unsigned)ix < 128u)
                v = __ldg(xc + iy * 128 + ix);
            ph[ki * 3 + kj] = v;
        }
    }
    const __half2* yb0 = (const __half2*)ybase + p * YSTR_H2;
    const __half2* yb1 = yb0 + YKG_H2;
    const float* bs = g_bias + t * 36 + 2 * h;
    float o0 = 0.f, o1 = 0.f;
    #pragma unroll
    for (int kk = 0; kk < 9; ++kk) {
        const int idx = kk * 2 + h;
        const float pv = ph[kk];
        float2 a = __half22float2(yb0[idx]);
        float2 c = __half22float2(yb1[idx]);
        float2 bb = *(const float2*)(bs + kk * 4);
        o0 += pv * fmaxf(a.x + c.x + bb.x, 0.f);
        o1 += pv * fmaxf(a.y + c.y + bb.y, 0.f);
    }
    const float inv9 = 1.f / 9.f;
    const size_t ob = ((size_t)(b * C_ + t) * 128 + 2 * oy + h) * 128 + 2 * ox;
    *(float2*)(out + ob) = make_float2(o0 * inv9, o1 * inv9);
}

// ---------------------------------------------------------------------------
// Main fused kernel: CTA = 128 pixels (16 oy x 8 ox), 2 CTAs/SM
// ---------------------------------------------------------------------------
__global__ __launch_bounds__(THREADS, 2)
void revo_hmma(const float* __restrict__ x, float* __restrict__ out) {
    extern __shared__ char smem[];
    __half* feat = (__half*)(smem + FEAT_OFF);
    float*  scr  = (float*)(smem + B1_OFF);    // borrows B1 during prologue
    const uint32_t sb = su32(smem);

    const int tid = threadIdx.x, lane = tid & 31, wid = tid >> 5;
    const int b = blockIdx.z, oy0 = blockIdx.y * 16, ox0 = blockIdx.x * 8;

    // stage weight chunk 0 early
    stage_b(sb + B0_OFF, 0, tid);
    cpcommit();

    // ---- feat build from GLOBAL x, parallel over (pixel, 16-channel group) --
    {
        const int p = tid & 127, cg = tid >> 7;   // cg = 0/1
        const int oyl = p >> 3, oxl = p & 7;
        const int oy = oy0 + oyl, ox = ox0 + oxl;
        __half* fr = feat + p * FSTR_H;
        int iy[3], ix[3];
        bool oky[3], okx[3];
        #pragma unroll
        for (int k3 = 0; k3 < 3; ++k3) {
            iy[k3] = 2 * oy - 1 + k3; oky[k3] = (unsigned)iy[k3] < 128u;
            ix[k3] = 2 * ox - 1 + k3; okx[k3] = (unsigned)ix[k3] < 128u;
        }
        float cm[9];
        #pragma unroll
        for (int kk = 0; kk < 9; ++kk) cm[kk] = -3.402823466e38f;
        #pragma unroll
        for (int cc = 0; cc < 16; ++cc) {
            const int c = cg * 16 + cc;
            const float* xc = x + ((size_t)(b * C_ + c) * 128) * 128;
            float ph[9];
            #pragma unroll
            for (int ki = 0; ki < 3; ++ki)
                #pragma unroll
                for (int kj = 0; kj < 3; ++kj) {
                    float v = 0.f;
                    if (oky[ki] && okx[kj]) v = __ldg(xc + iy[ki] * 128 + ix[kj]);
                    ph[ki * 3 + kj] = v;
                }
            #pragma unroll
            for (int kk = 0; kk < 9; ++kk) cm[kk] = fmaxf(cm[kk], ph[kk]);
            #pragma unroll
            for (int j = 0; j < 3; ++j)
                fr[9 + c * 3 + j] =
                    __float2half_rn(fmaxf(fmaxf(ph[j], ph[3 + j]), ph[6 + j]));
            #pragma unroll
            for (int i = 0; i < 3; ++i)
                fr[105 + c * 3 + i] =
                    __float2half_rn(fmaxf(fmaxf(ph[3 * i], ph[3 * i + 1]), ph[3 * i + 2]));
        }
        #pragma unroll
        for (int kk = 0; kk < 9; ++kk) scr[p * 18 + cg * 9 + kk] = cm[kk];
    }
    __syncthreads();
    for (int e = tid; e < 128 * 9; e += THREADS) {
        int p = e / 9, kk = e - p * 9;
        feat[p * FSTR_H + kk] =
            __float2half_rn(fmaxf(scr[p * 18 + kk], scr[p * 18 + 9 + kk]));
    }
    if (tid < 128) {
        #pragma unroll
        for (int k = INCH; k < KH; ++k)
            feat[tid * FSTR_H + k] = __ushort_as_half(0);
    }
    // zero pad rows 36..39 of both B buffers (scr no longer needed)
    for (int e = tid; e < 2 * 4 * 27; e += THREADS) {
        int buf = e / 108, r = (e / 27) & 3, q = e % 27;
        *(uint4*)(smem + (buf ? B1_OFF : B0_OFF) + (36 + r) * FSTR_B + q * 16) =
            make_uint4(0, 0, 0, 0);
    }
    __syncthreads();

    // warp roles: 4 M-groups (32 rows) x 2 K-groups (ksteps 0-6 / 7-12)
    const int mgrp = wid >> 1, kgrp = wid & 1;
    const int m0 = mgrp * 32;
    const int ks0 = kgrp * 7;
    const int nks = 7 - kgrp;          // 7 or 6
    const int g = lane >> 2, tg = lane & 3;

    // preload this warp's A fragments (<= 56 regs); feat dead afterwards
    uint32_t afr[7][2][4];
    #pragma unroll
    for (int i = 0; i < 7; ++i) {
        if (i < nks) {
            #pragma unroll
            for (int mt = 0; mt < 2; ++mt)
                ldsm4(afr[i][mt],
                      sb + FEAT_OFF + (uint32_t)(m0 + mt * 16 + (lane & 15)) * FSTR_B
                      + (ks0 + i) * 32 + (lane >> 4) * 16);
        }
    }
    __syncthreads();   // all afr loaded before ybuf overwrites feat region

    // ---- pipelined loop: stage(t+1) | GEMM(t) | epilogue(t-1) ----
    for (int t = 0; t < NCHUNKS; ++t) {
        if (t + 1 < NCHUNKS)
            stage_b(sb + (((t + 1) & 1) ? B1_OFF : B0_OFF), (t + 1) * NCH, tid);
        cpcommit();
        cpwait1();

        const uint32_t bb = sb + ((t & 1) ? B1_OFF : B0_OFF);
        float acc[5][2][4];
        #pragma unroll
        for (int i = 0; i < 5; ++i)
            #pragma unroll
            for (int j = 0; j < 2; ++j)
                #pragma unroll
                for (int k = 0; k < 4; ++k) acc[i][j][k] = 0.f;

        gemm_chunk(afr, ks0, nks, bb, lane, acc);

        // K-partial C frags -> this kgrp's ybuf plane (fp16)
        __half2* ybw = (__half2*)(smem + YB_OFF + (t & 1) * YBUF_BYTES
                                  + kgrp * YKG_BYTES);
        #pragma unroll
        for (int nt = 0; nt < 5; ++nt) {
            const int h2i = nt * 4 + tg;
            #pragma unroll
            for (int mt = 0; mt < 2; ++mt) {
                const int p0 = m0 + mt * 16 + g;
                ybw[p0 * YSTR_H2 + h2i] =
                    __floats2half2_rn(acc[nt][mt][0], acc[nt][mt][1]);
                ybw[(p0 + 8) * YSTR_H2 + h2i] =
                    __floats2half2_rn(acc[nt][mt][2], acc[nt][mt][3]);
            }
        }

        if (t > 0)
            epilogue(t - 1, smem + YB_OFF + ((t - 1) & 1) * YBUF_BYTES,
                     x, out, tid, b, oy0, ox0);
        __syncthreads();
    }
    epilogue(NCHUNKS - 1, smem + YB_OFF + ((NCHUNKS - 1) & 1) * YBUF_BYTES,
             x, out, tid, b, oy0, ox0);
}

// ---------------------------------------------------------------------------
extern "C" void kernel_launch(void* const* d_in, const int* in_sizes, int n_in,
                              void* d_out, int out_size) {
    const float* x   = (const float*)d_in[0];
    const float* cw  = (const float*)d_in[1];
    const float* gam = (const float*)d_in[2];
    const float* bet = (const float*)d_in[3];
    const float* mn  = (const float*)d_in[4];
    const float* vr  = (const float*)d_in[5];
    float* out       = (float*)d_out;

    cudaFuncSetAttribute(revo_hmma, cudaFuncAttributeMaxDynamicSharedMemorySize,
                         SMEM_BYTES);

    repack_kernel<<<1152, 128>>>(cw, gam, bet, mn, vr);
    dim3 grid(8, 4, B_);   // 256 CTAs, 2 resident per SM -> single wave
    revo_hmma<<<grid, THREADS, SMEM_BYTES>>>(x, out);
}